// round 1
// baseline (speedup 1.0000x reference)
#include <cuda_runtime.h>
#include <math.h>

// Problem constants
#define NUM_R 8
#define KLEN  128
#define HID   32
#define B2N   16384
#define LREC  4096

// Prefix-sum tables over W1:
//   g_PA[r][k][h] = sum_{j<k} W1[(r*KLEN+j)*HID + h]
//   g_PB[r][k][h] = sum_{j<k} j * W1[(r*KLEN+j)*HID + h]
__device__ float g_PA[NUM_R][KLEN + 1][HID];
__device__ float g_PB[NUM_R][KLEN + 1][HID];

// Build prefix tables. One block per r; 256 threads = (32 h) x (8 segments of 16 k's).
__global__ void prep_kernel(const float* __restrict__ W1) {
    int r   = blockIdx.x;
    int h   = threadIdx.x & 31;
    int seg = threadIdx.x >> 5;   // 0..7
    __shared__ float sA[8][HID];
    __shared__ float sB[8][HID];

    int k0 = seg * 16;
    float a = 0.f, b = 0.f;
    if (seg == 0) {
        g_PA[r][0][h] = 0.f;
        g_PB[r][0][h] = 0.f;
    }
#pragma unroll
    for (int j = 0; j < 16; ++j) {
        int k = k0 + j;
        float w = W1[(r * KLEN + k) * HID + h];
        a += w;
        b += (float)k * w;
        g_PA[r][k + 1][h] = a;
        g_PB[r][k + 1][h] = b;
    }
    sA[seg][h] = a;
    sB[seg][h] = b;
    __syncthreads();

    float offA = 0.f, offB = 0.f;
    for (int s = 0; s < seg; ++s) { offA += sA[s][h]; offB += sB[s][h]; }
    if (seg > 0) {
#pragma unroll
        for (int j = 0; j < 16; ++j) {
            int k = k0 + j;
            g_PA[r][k + 1][h] += offA;
            g_PB[r][k + 1][h] += offB;
        }
    }
}

// Main kernel: one warp per (b1,b2) sample, lane = hidden unit.
__global__ void __launch_bounds__(256) tof_kernel(
    const float* __restrict__ rec,    // (B1, R, LREC)
    const float* __restrict__ sloc,   // (B1, B2, 3)
    const float* __restrict__ emit,   // (3,)
    const float* __restrict__ rloc,   // (R, 3)
    const float* __restrict__ b1v,    // (HID,)
    const float* __restrict__ W2,     // (HID, 1)
    const float* __restrict__ b2v,    // (1,)
    float* __restrict__ out,          // (B1, B2)
    int total)
{
    int warp_id = (int)((blockIdx.x * (unsigned)blockDim.x + threadIdx.x) >> 5);
    int lane = threadIdx.x & 31;
    if (warp_id >= total) return;

    int b1i = warp_id >> 14;           // / B2N

    // emitter distance
    float ex = emit[0], ey = emit[1], ez = emit[2];
    const float* sp = sloc + (size_t)warp_id * 3;
    float sx = sp[0], sy = sp[1], sz = sp[2];
    float dx = sx - ex, dy = sy - ey, dz = sz - ez;
    float de = sqrtf(dx * dx + dy * dy + dz * dz);

    float acc = 0.f;
    const float inv = 1.0f / 16384.0f;

#pragma unroll
    for (int r = 0; r < NUM_R; ++r) {
        float rx = rloc[r * 3 + 0], ry = rloc[r * 3 + 1], rz = rloc[r * 3 + 2];
        float qx = sx - rx, qy = sy - ry, qz = sz - rz;
        float dr = sqrtf(qx * qx + qy * qy + qz * qz);

        // total_samples = round((de+dr)/343*96000); cs = total - K/2
        float t = (de + dr) / 343.0f * 96000.0f;
        int cs = (int)rintf(t) - (KLEN / 2);
        // ix_k = (4*cs + k - 8192)/16384 exactly (fp32-exact integer numerator)
        int m0 = 4 * cs - 8192;

        const float* recr = rec + ((size_t)(b1i * NUM_R + r)) * LREC;
        float vyr = 0.5f * recr[2047] + 0.5f * recr[2048];

        // Triangle weight w(m) = 1 + m/16384 for m in [-16384,0),
        //                  w(m) = 1 - m/16384 for m in [0,16384), else 0.
        // Segment bounds in k (clamped to [0,KLEN]); warp-uniform.
        int ka = max(min(-16384 - m0, KLEN), 0);
        int kb = max(min(-m0,          KLEN), 0);
        int kd = max(min(16384 - m0,   KLEN), 0);
        float m0f = (float)m0;

        const float* PAr = &g_PA[r][0][0];
        const float* PBr = &g_PB[r][0][0];

        if (kb > ka) {  // negative-m side: w = 1 + (m0+k)/16384
            float pa = PAr[kb * HID + lane] - PAr[ka * HID + lane];
            float pb = PBr[kb * HID + lane] - PBr[ka * HID + lane];
            acc += vyr * (fmaf(m0f, inv, 1.0f) * pa + inv * pb);
        }
        if (kd > kb) {  // positive-m side: w = 1 - (m0+k)/16384
            float pa = PAr[kd * HID + lane] - PAr[kb * HID + lane];
            float pb = PBr[kd * HID + lane] - PBr[kb * HID + lane];
            acc += vyr * (fmaf(-m0f, inv, 1.0f) * pa - inv * pb);
        }
    }

    // MLP head: relu(acc + b1) dot W2 + b2, reduced across the warp
    float hv = fmaxf(acc + b1v[lane], 0.0f);
    float c = hv * W2[lane];
#pragma unroll
    for (int off = 16; off; off >>= 1)
        c += __shfl_xor_sync(0xffffffffu, c, off);
    if (lane == 0) out[warp_id] = c + b2v[0];
}

extern "C" void kernel_launch(void* const* d_in, const int* in_sizes, int n_in,
                              void* d_out, int out_size) {
    const float* rec  = (const float*)d_in[0];
    const float* sloc = (const float*)d_in[1];
    const float* emit = (const float*)d_in[2];
    const float* rloc = (const float*)d_in[3];
    const float* W1   = (const float*)d_in[4];
    const float* b1v  = (const float*)d_in[5];
    const float* W2   = (const float*)d_in[6];
    const float* b2v  = (const float*)d_in[7];
    float* out = (float*)d_out;

    prep_kernel<<<NUM_R, 256>>>(W1);

    int total = out_size;              // B1*B2 = 65536 samples, one warp each
    int threads = 256;                 // 8 warps per block
    int blocks = (total * 32 + threads - 1) / threads;
    tof_kernel<<<blocks, threads>>>(rec, sloc, emit, rloc, b1v, W2, b2v, out, total);
}

// round 2
// speedup vs baseline: 1.9917x; 1.9917x over previous
#include <cuda_runtime.h>
#include <math.h>

// Problem constants
#define NUM_R 8
#define KLEN  128
#define HID   32
#define LREC  4096
#define KP1   (KLEN + 1)

// Interleaved prefix-sum tables over W1:
//   g_P[r][k][0][h] = sum_{j<k} W1[(r*KLEN+j)*HID + h]          (PA)
//   g_P[r][k][1][h] = sum_{j<k} j * W1[(r*KLEN+j)*HID + h]      (PB)
__device__ float g_P[NUM_R][KP1][2][HID];

// Build prefix tables. One block per r; 256 threads = (32 h) x (8 segments of 16 k's).
__global__ void prep_kernel(const float* __restrict__ W1) {
    int r   = blockIdx.x;
    int h   = threadIdx.x & 31;
    int seg = threadIdx.x >> 5;   // 0..7
    __shared__ float sA[8][HID];
    __shared__ float sB[8][HID];

    int k0 = seg * 16;
    float a = 0.f, b = 0.f;
    if (seg == 0) {
        g_P[r][0][0][h] = 0.f;
        g_P[r][0][1][h] = 0.f;
    }
#pragma unroll
    for (int j = 0; j < 16; ++j) {
        int k = k0 + j;
        float w = W1[(r * KLEN + k) * HID + h];
        a += w;
        b += (float)k * w;
        g_P[r][k + 1][0][h] = a;
        g_P[r][k + 1][1][h] = b;
    }
    sA[seg][h] = a;
    sB[seg][h] = b;
    __syncthreads();

    float offA = 0.f, offB = 0.f;
    for (int s = 0; s < seg; ++s) { offA += sA[s][h]; offB += sB[s][h]; }
    if (seg > 0) {
#pragma unroll
        for (int j = 0; j < 16; ++j) {
            int k = k0 + j;
            g_P[r][k + 1][0][h] += offA;
            g_P[r][k + 1][1][h] += offB;
        }
    }
}

// Main kernel: one warp per (b1,b2) sample, lane = hidden unit.
// Geometry for the 8 receivers is computed in parallel by lanes 0..7 and
// broadcast via shuffles; the hidden-dim table work uses a 2-load fast path.
__global__ void __launch_bounds__(256) tof_kernel(
    const float* __restrict__ rec,    // (B1, R, LREC)
    const float* __restrict__ sloc,   // (B1, B2, 3)
    const float* __restrict__ emit,   // (3,)
    const float* __restrict__ rloc,   // (R, 3)
    const float* __restrict__ b1v,    // (HID,)
    const float* __restrict__ W2,     // (HID, 1)
    const float* __restrict__ b2v,    // (1,)
    float* __restrict__ out,          // (B1, B2)
    int total)
{
    int warp_id = (int)((blockIdx.x * (unsigned)blockDim.x + threadIdx.x) >> 5);
    int lane = threadIdx.x & 31;
    if (warp_id >= total) return;

    int b1i = warp_id >> 14;           // / B2 (=16384)

    const float inv  = 1.0f / 16384.0f;
    const float inv2 = 2.0f / 16384.0f;

    // ---- Phase 1: lane r in [0,8) computes m0_r and vy_r for this sample ----
    int   m0v = 0;
    float vyv = 0.f;
    int   okv = 1;
    const float* sp = sloc + (size_t)warp_id * 3;
    if (lane < NUM_R) {
        float sx = sp[0], sy = sp[1], sz = sp[2];
        float dx = sx - emit[0], dy = sy - emit[1], dz = sz - emit[2];
        float de = sqrtf(dx * dx + dy * dy + dz * dz);
        const float* rp = rloc + lane * 3;
        float qx = sx - rp[0], qy = sy - rp[1], qz = sz - rp[2];
        float dr = sqrtf(qx * qx + qy * qy + qz * qz);
        // keep exact reference order: /343 then *96000 (bit-matches rintf boundary)
        float t = (de + dr) / 343.0f * 96000.0f;
        int cs = (int)rintf(t) - (KLEN / 2);
        m0v = 4 * cs - 8192;           // ix numerator: ix_k = (m0 + k)/16384
        const float* recr = rec + (size_t)(b1i * NUM_R + lane) * LREC;
        vyv = 0.5f * recr[2047] + 0.5f * recr[2048];
        // fast path valid iff ka==0 (m0 >= -16384) and kd==128 (m0 <= 16256)
        okv = (m0v >= -16384) && (m0v <= 16256);
    }
    bool fast = __all_sync(0xffffffffu, okv != 0);

    // ---- Preload per-(r,lane) endpoint values: A=PA[128], base=A - inv*PB[128] ----
    float Aend[NUM_R], Base[NUM_R];
#pragma unroll
    for (int r = 0; r < NUM_R; ++r) {
        float a = g_P[r][KLEN][0][lane];
        float b = g_P[r][KLEN][1][lane];
        Aend[r] = a;
        Base[r] = fmaf(-inv, b, a);
    }

    float acc = 0.f;
    if (fast) {
#pragma unroll
        for (int r = 0; r < NUM_R; ++r) {
            int   m0 = __shfl_sync(0xffffffffu, m0v, r);
            float vy = __shfl_sync(0xffffffffu, vyv, r);
            int   kb = max(min(-m0, KLEN), 0);
            float m0f = (float)m0;
            const float* p = &g_P[r][kb][0][lane];
            float pa = p[0];
            float pb = p[HID];               // +128 bytes: interleaved PB
            // S = (1-u)A - inv*B + 2u*pa + 2inv*pb,  u = m0/16384
            float u  = m0f * inv;
            float t1 = fmaf(-u, Aend[r], Base[r]);
            float t2 = fmaf(m0f * inv2, pa, t1);
            float t3 = fmaf(inv2, pb, t2);
            acc = fmaf(vy, t3, acc);
        }
    } else {
        // General (rare) path: full two-segment form with clamps.
#pragma unroll
        for (int r = 0; r < NUM_R; ++r) {
            int   m0 = __shfl_sync(0xffffffffu, m0v, r);
            float vy = __shfl_sync(0xffffffffu, vyv, r);
            int ka = max(min(-16384 - m0, KLEN), 0);
            int kb = max(min(-m0,          KLEN), 0);
            int kd = max(min(16384 - m0,   KLEN), 0);
            float m0f = (float)m0;
            if (kb > ka) {  // w = 1 + (m0+k)/16384
                float pa = g_P[r][kb][0][lane] - g_P[r][ka][0][lane];
                float pb = g_P[r][kb][1][lane] - g_P[r][ka][1][lane];
                acc += vy * (fmaf(m0f, inv, 1.0f) * pa + inv * pb);
            }
            if (kd > kb) {  // w = 1 - (m0+k)/16384
                float pa = g_P[r][kd][0][lane] - g_P[r][kb][0][lane];
                float pb = g_P[r][kd][1][lane] - g_P[r][kb][1][lane];
                acc += vy * (fmaf(-m0f, inv, 1.0f) * pa - inv * pb);
            }
        }
    }

    // ---- MLP head: relu(acc + b1) dot W2 + b2, warp reduction ----
    float hv = fmaxf(acc + b1v[lane], 0.0f);
    float c = hv * W2[lane];
#pragma unroll
    for (int off = 16; off; off >>= 1)
        c += __shfl_xor_sync(0xffffffffu, c, off);
    if (lane == 0) out[warp_id] = c + b2v[0];
}

extern "C" void kernel_launch(void* const* d_in, const int* in_sizes, int n_in,
                              void* d_out, int out_size) {
    const float* rec  = (const float*)d_in[0];
    const float* sloc = (const float*)d_in[1];
    const float* emit = (const float*)d_in[2];
    const float* rloc = (const float*)d_in[3];
    const float* W1   = (const float*)d_in[4];
    const float* b1v  = (const float*)d_in[5];
    const float* W2   = (const float*)d_in[6];
    const float* b2v  = (const float*)d_in[7];
    float* out = (float*)d_out;

    prep_kernel<<<NUM_R, 256>>>(W1);

    int total = out_size;              // B1*B2 = 65536 samples, one warp each
    int threads = 256;                 // 8 warps per block
    int blocks = (total * 32 + threads - 1) / threads;
    tof_kernel<<<blocks, threads>>>(rec, sloc, emit, rloc, b1v, W2, b2v, out, total);
}

// round 3
// speedup vs baseline: 2.1327x; 1.0708x over previous
#include <cuda_runtime.h>
#include <math.h>

// Problem constants
#define NUM_R 8
#define KLEN  128
#define HID   32
#define LREC  4096
#define KP1   (KLEN + 1)
#define MAXB1 16

// Fast-path folded table: S(kb,u) = C.x + u * C.y  (per r, lane)
//   C.x = (PA[128] - inv*PB[128]) + 2*inv*PB[k]
//   C.y = 2*PA[k] - PA[128]
__device__ float2 g_C[NUM_R][KP1][HID];
// Raw prefix tables for the (rare) general fallback path
__device__ float  g_P[NUM_R][KP1][2][HID];
// vy[b1][r] = 0.5*(rec[b1,r,2047] + rec[b1,r,2048])
__device__ float  g_vy[MAXB1][NUM_R];

// One block per r; 256 threads = (32 h) x (8 segments of 16 k's).
__global__ void prep_kernel(const float* __restrict__ W1,
                            const float* __restrict__ rec, int nb1) {
    int r   = blockIdx.x;
    int h   = threadIdx.x & 31;
    int seg = threadIdx.x >> 5;   // 0..7
    __shared__ float sA[KP1][HID];
    __shared__ float sB[KP1][HID];
    __shared__ float sTA[8][HID];
    __shared__ float sTB[8][HID];

    // vy table (cheap, independent)
    if (threadIdx.x < nb1) {
        const float* rr = rec + (size_t)(threadIdx.x * NUM_R + r) * LREC;
        g_vy[threadIdx.x][r] = 0.5f * rr[2047] + 0.5f * rr[2048];
    }

    int k0 = seg * 16;
    float a = 0.f, b = 0.f;
    if (seg == 0) { sA[0][h] = 0.f; sB[0][h] = 0.f; }
#pragma unroll
    for (int j = 0; j < 16; ++j) {
        int k = k0 + j;
        float w = W1[(r * KLEN + k) * HID + h];
        a += w;
        b += (float)k * w;
        sA[k + 1][h] = a;
        sB[k + 1][h] = b;
    }
    sTA[seg][h] = a;
    sTB[seg][h] = b;
    __syncthreads();

    float offA = 0.f, offB = 0.f;
    for (int s = 0; s < seg; ++s) { offA += sTA[s][h]; offB += sTB[s][h]; }
    if (seg > 0) {
#pragma unroll
        for (int j = 0; j < 16; ++j) {
            int k = k0 + j;
            sA[k + 1][h] += offA;
            sB[k + 1][h] += offB;
        }
    }
    __syncthreads();

    const float inv  = 1.0f / 16384.0f;
    const float inv2 = 2.0f / 16384.0f;
    float Aend = sA[KLEN][h];
    float Bend = sB[KLEN][h];
    float Base = fmaf(-inv, Bend, Aend);
    for (int k = seg; k < KP1; k += 8) {
        float pa = sA[k][h], pb = sB[k][h];
        float2 c;
        c.x = fmaf(inv2, pb, Base);
        c.y = fmaf(2.0f, pa, -Aend);
        g_C[r][k][h] = c;
        g_P[r][k][0][h] = pa;
        g_P[r][k][1][h] = pb;
    }
}

// Main kernel: one warp per (b1,b2) sample, lane = hidden unit.
__global__ void __launch_bounds__(256) tof_kernel(
    const float* __restrict__ sloc,   // (B1, B2, 3)
    const float* __restrict__ emit,   // (3,)
    const float* __restrict__ rloc,   // (R, 3)
    const float* __restrict__ b1v,    // (HID,)
    const float* __restrict__ W2,     // (HID, 1)
    const float* __restrict__ b2v,    // (1,)
    float* __restrict__ out,          // (B1, B2)
    int total, int b2n)
{
    int warp_id = (int)((blockIdx.x * (unsigned)blockDim.x + threadIdx.x) >> 5);
    int lane = threadIdx.x & 31;
    if (warp_id >= total) return;

    int b1i = (int)((unsigned)warp_id / (unsigned)b2n);

    const float inv = 1.0f / 16384.0f;

    // ---- Phase 1: lane r in [0,8) computes m0_r, vy_r ----
    int   m0v = 0;
    float vyv = 0.f;
    int   okv = 1;
    const float* sp = sloc + (size_t)warp_id * 3;
    if (lane < NUM_R) {
        float sx = sp[0], sy = sp[1], sz = sp[2];
        float dx = sx - emit[0], dy = sy - emit[1], dz = sz - emit[2];
        float de = sqrtf(dx * dx + dy * dy + dz * dz);
        const float* rp = rloc + lane * 3;
        float qx = sx - rp[0], qy = sy - rp[1], qz = sz - rp[2];
        float dr = sqrtf(qx * qx + qy * qy + qz * qz);
        float t = (de + dr) / 343.0f * 96000.0f;  // exact reference order
        int cs = (int)rintf(t) - (KLEN / 2);
        m0v = 4 * cs - 8192;
        vyv = g_vy[b1i][lane];
        okv = (m0v >= -16384) && (m0v <= 16384 - KLEN);
    }
    bool fast = __all_sync(0xffffffffu, okv != 0);

    float acc = 0.f;
    if (fast) {
#pragma unroll
        for (int r = 0; r < NUM_R; ++r) {
            int   m0 = __shfl_sync(0xffffffffu, m0v, r);
            float vy = __shfl_sync(0xffffffffu, vyv, r);
            int   kb = max(min(-m0, KLEN), 0);
            float u  = (float)m0 * inv;
            float2 c = g_C[r][kb][lane];
            acc = fmaf(vy, fmaf(u, c.y, c.x), acc);
        }
    } else {
        // General path: full two-segment form with clamps.
#pragma unroll
        for (int r = 0; r < NUM_R; ++r) {
            int   m0 = __shfl_sync(0xffffffffu, m0v, r);
            float vy = __shfl_sync(0xffffffffu, vyv, r);
            int ka = max(min(-16384 - m0, KLEN), 0);
            int kb = max(min(-m0,          KLEN), 0);
            int kd = max(min(16384 - m0,   KLEN), 0);
            float m0f = (float)m0;
            if (kb > ka) {  // w = 1 + (m0+k)/16384
                float pa = g_P[r][kb][0][lane] - g_P[r][ka][0][lane];
                float pb = g_P[r][kb][1][lane] - g_P[r][ka][1][lane];
                acc += vy * (fmaf(m0f, inv, 1.0f) * pa + inv * pb);
            }
            if (kd > kb) {  // w = 1 - (m0+k)/16384
                float pa = g_P[r][kd][0][lane] - g_P[r][kb][0][lane];
                float pb = g_P[r][kd][1][lane] - g_P[r][kb][1][lane];
                acc += vy * (fmaf(-m0f, inv, 1.0f) * pa - inv * pb);
            }
        }
    }

    // ---- MLP head: relu(acc + b1) dot W2 + b2, warp reduction ----
    float hv = fmaxf(acc + b1v[lane], 0.0f);
    float c = hv * W2[lane];
#pragma unroll
    for (int off = 16; off; off >>= 1)
        c += __shfl_xor_sync(0xffffffffu, c, off);
    if (lane == 0) out[warp_id] = c + b2v[0];
}

extern "C" void kernel_launch(void* const* d_in, const int* in_sizes, int n_in,
                              void* d_out, int out_size) {
    const float* rec  = (const float*)d_in[0];
    const float* sloc = (const float*)d_in[1];
    const float* emit = (const float*)d_in[2];
    const float* rloc = (const float*)d_in[3];
    const float* W1   = (const float*)d_in[4];
    const float* b1v  = (const float*)d_in[5];
    const float* W2   = (const float*)d_in[6];
    const float* b2v  = (const float*)d_in[7];
    float* out = (float*)d_out;

    int nb1 = in_sizes[0] / (NUM_R * LREC);       // B1
    if (nb1 > MAXB1) nb1 = MAXB1;
    int b2n = (in_sizes[1] / 3) / (nb1 > 0 ? nb1 : 1);   // B2

    prep_kernel<<<NUM_R, 256>>>(W1, rec, nb1);

    int total = out_size;              // B1*B2 samples, one warp each
    int threads = 256;                 // 8 warps per block
    int blocks = (total * 32 + threads - 1) / threads;
    tof_kernel<<<blocks, threads>>>(sloc, emit, rloc, b1v, W2, b2v, out,
                                    total, b2n);
}

// round 4
// speedup vs baseline: 2.4736x; 1.1598x over previous
#include <cuda_runtime.h>
#include <math.h>

// Problem constants
#define NUM_R 8
#define KLEN  128
#define HID   32
#define LREC  4096
#define KP1   (KLEN + 1)
#define MAXB1 16
#define MAXS  (1 << 17)

// vy-folded fast-path table: contribution of receiver r for sample in batch b1:
//   S = c.x + u * c.y, with vy baked in.
__device__ float2 g_C[MAXB1][NUM_R][KP1][HID];
// Raw prefix tables (PA, PB) for the general fallback path (also used as
// prep scratch, ordered by __syncthreads within each prep block).
__device__ float  g_P[NUM_R][KP1][2][HID];
// vy[b1][r] for the fallback path
__device__ float  g_vy[MAXB1][NUM_R];
// Per-(sample, r) geometry result: {table byte-offset or -1, u}
__device__ float2 g_G[MAXS * NUM_R];

// Merged kernel: blocks [0, prep_blocks) build tables (one block per (b1,r));
// remaining blocks run thread-per-(sample, r) geometry.
__global__ void __launch_bounds__(256) prep_geom_kernel(
    const float* __restrict__ W1,
    const float* __restrict__ rec,
    const float* __restrict__ sloc,
    const float* __restrict__ emit,
    const float* __restrict__ rloc,
    int prep_blocks, int total, int b2n)
{
    const float inv  = 1.0f / 16384.0f;
    if ((int)blockIdx.x < prep_blocks) {
        __shared__ float sTA[8][HID];
        __shared__ float sTB[8][HID];
        int r   = blockIdx.x & (NUM_R - 1);
        int b1  = blockIdx.x >> 3;
        int h   = threadIdx.x & 31;
        int seg = threadIdx.x >> 5;   // 0..7, 16 k's each

        int k0 = seg * 16;
        float a = 0.f, b = 0.f;
        if (seg == 0) { g_P[r][0][0][h] = 0.f; g_P[r][0][1][h] = 0.f; }
#pragma unroll
        for (int j = 0; j < 16; ++j) {
            int k = k0 + j;
            float w = W1[(r * KLEN + k) * HID + h];
            a += w;
            b += (float)k * w;
            g_P[r][k + 1][0][h] = a;
            g_P[r][k + 1][1][h] = b;
        }
        sTA[seg][h] = a;
        sTB[seg][h] = b;
        __syncthreads();

        float offA = 0.f, offB = 0.f;
        for (int s = 0; s < seg; ++s) { offA += sTA[s][h]; offB += sTB[s][h]; }
        if (seg > 0) {
#pragma unroll
            for (int j = 0; j < 16; ++j) {
                int k = k0 + j;
                g_P[r][k + 1][0][h] += offA;
                g_P[r][k + 1][1][h] += offB;
            }
        }
        __syncthreads();   // all of g_P[r] final & visible within this block

        const float* rr = rec + (size_t)(b1 * NUM_R + r) * LREC;
        float vy = 0.5f * rr[2047] + 0.5f * rr[2048];
        if (threadIdx.x == 0) g_vy[b1][r] = vy;

        const float inv2 = 2.0f / 16384.0f;
        float Aend = g_P[r][KLEN][0][h];
        float Bend = g_P[r][KLEN][1][h];
        float Base = fmaf(-inv, Bend, Aend);
        for (int k = seg; k < KP1; k += 8) {
            float pa = g_P[r][k][0][h], pb = g_P[r][k][1][h];
            float2 c;
            c.x = vy * fmaf(inv2, pb, Base);
            c.y = vy * fmaf(2.0f, pa, -Aend);
            g_C[b1][r][k][h] = c;
        }
    } else {
        int t = (int)(blockIdx.x - prep_blocks) * 256 + (int)threadIdx.x;
        if (t >= total * NUM_R) return;
        int s = t >> 3;
        int r = t & 7;
        int b1 = (int)((unsigned)s / (unsigned)b2n);

        const float* sp = sloc + (size_t)s * 3;
        float sx = sp[0], sy = sp[1], sz = sp[2];
        float dx = sx - emit[0], dy = sy - emit[1], dz = sz - emit[2];
        float de = sqrtf(dx * dx + dy * dy + dz * dz);
        const float* rp = rloc + r * 3;
        float qx = sx - rp[0], qy = sy - rp[1], qz = sz - rp[2];
        float dr = sqrtf(qx * qx + qy * qy + qz * qz);
        float tt = (de + dr) / 343.0f * 96000.0f;   // exact reference order
        int cs = (int)rintf(tt) - (KLEN / 2);
        int m0 = 4 * cs - 8192;
        int kb = max(min(-m0, KLEN), 0);
        bool ok = (m0 >= -16384) && (m0 <= 16384 - KLEN);
        int off = (((b1 * NUM_R + r) * KP1 + kb) * HID) * 8;   // byte offset
        float u = (float)m0 * inv;                              // exact
        g_G[t] = make_float2(__int_as_float(ok ? off : -1), u);
    }
}

// Hot kernel: one warp per sample, lane = hidden unit. No shuffles, no sqrt,
// no divides: 4 uniform LDG.128 + 8 per-lane LDG.64 + 16 FMA + epilogue.
__global__ void __launch_bounds__(256) tof_kernel(
    const float* __restrict__ b1v,    // (HID,)
    const float* __restrict__ W2,     // (HID,)
    const float* __restrict__ b2v,    // (1,)
    float* __restrict__ out,          // (B1*B2,)
    int total, int b2n)
{
    int warp_id = (int)((blockIdx.x * (unsigned)blockDim.x + threadIdx.x) >> 5);
    int lane = threadIdx.x & 31;
    if (warp_id >= total) return;

    const float4* G4 = (const float4*)(g_G + (size_t)warp_id * NUM_R);
    float4 q0 = G4[0], q1 = G4[1], q2 = G4[2], q3 = G4[3];
    int sgn = __float_as_int(q0.x) | __float_as_int(q0.z)
            | __float_as_int(q1.x) | __float_as_int(q1.z)
            | __float_as_int(q2.x) | __float_as_int(q2.z)
            | __float_as_int(q3.x) | __float_as_int(q3.z);

    float acc;
    const char* base = (const char*)(&g_C[0][0][0][0]) + lane * 8;
    if (sgn >= 0) {
        float2 c;
        float acc0 = 0.f, acc1 = 0.f;
        c = *(const float2*)(base + __float_as_int(q0.x)); acc0 = fmaf(q0.y, c.y, acc0 + c.x);
        c = *(const float2*)(base + __float_as_int(q0.z)); acc1 = fmaf(q0.w, c.y, acc1 + c.x);
        c = *(const float2*)(base + __float_as_int(q1.x)); acc0 = fmaf(q1.y, c.y, acc0 + c.x);
        c = *(const float2*)(base + __float_as_int(q1.z)); acc1 = fmaf(q1.w, c.y, acc1 + c.x);
        c = *(const float2*)(base + __float_as_int(q2.x)); acc0 = fmaf(q2.y, c.y, acc0 + c.x);
        c = *(const float2*)(base + __float_as_int(q2.z)); acc1 = fmaf(q2.w, c.y, acc1 + c.x);
        c = *(const float2*)(base + __float_as_int(q3.x)); acc0 = fmaf(q3.y, c.y, acc0 + c.x);
        c = *(const float2*)(base + __float_as_int(q3.z)); acc1 = fmaf(q3.w, c.y, acc1 + c.x);
        acc = acc0 + acc1;
    } else {
        // General (rare) fallback: reconstruct m0 exactly from u.
        const float inv = 1.0f / 16384.0f;
        int b1 = (int)((unsigned)warp_id / (unsigned)b2n);
        acc = 0.f;
#pragma unroll
        for (int r = 0; r < NUM_R; ++r) {
            float2 g = g_G[(size_t)warp_id * NUM_R + r];
            int m0 = __float2int_rn(g.y * 16384.0f);   // exact recovery
            float vy = g_vy[b1][r];
            int ka = max(min(-16384 - m0, KLEN), 0);
            int kb = max(min(-m0,          KLEN), 0);
            int kd = max(min(16384 - m0,   KLEN), 0);
            float m0f = (float)m0;
            if (kb > ka) {  // w = 1 + (m0+k)/16384
                float pa = g_P[r][kb][0][lane] - g_P[r][ka][0][lane];
                float pb = g_P[r][kb][1][lane] - g_P[r][ka][1][lane];
                acc += vy * (fmaf(m0f, inv, 1.0f) * pa + inv * pb);
            }
            if (kd > kb) {  // w = 1 - (m0+k)/16384
                float pa = g_P[r][kd][0][lane] - g_P[r][kb][0][lane];
                float pb = g_P[r][kd][1][lane] - g_P[r][kb][1][lane];
                acc += vy * (fmaf(-m0f, inv, 1.0f) * pa - inv * pb);
            }
        }
    }

    // MLP head: relu(acc + b1) dot W2 + b2, warp reduction
    float hv = fmaxf(acc + b1v[lane], 0.0f);
    float c = hv * W2[lane];
#pragma unroll
    for (int off = 16; off; off >>= 1)
        c += __shfl_xor_sync(0xffffffffu, c, off);
    if (lane == 0) out[warp_id] = c + b2v[0];
}

extern "C" void kernel_launch(void* const* d_in, const int* in_sizes, int n_in,
                              void* d_out, int out_size) {
    const float* rec  = (const float*)d_in[0];
    const float* sloc = (const float*)d_in[1];
    const float* emit = (const float*)d_in[2];
    const float* rloc = (const float*)d_in[3];
    const float* W1   = (const float*)d_in[4];
    const float* b1v  = (const float*)d_in[5];
    const float* W2   = (const float*)d_in[6];
    const float* b2v  = (const float*)d_in[7];
    float* out = (float*)d_out;

    int nb1 = in_sizes[0] / (NUM_R * LREC);       // B1
    if (nb1 < 1) nb1 = 1;
    if (nb1 > MAXB1) nb1 = MAXB1;
    int total = out_size;                         // B1*B2 samples
    if (total > MAXS) total = MAXS;
    int b2n = total / nb1;

    int prep_blocks = NUM_R * nb1;
    int geom_threads = total * NUM_R;
    int blocksA = prep_blocks + (geom_threads + 255) / 256;
    prep_geom_kernel<<<blocksA, 256>>>(W1, rec, sloc, emit, rloc,
                                       prep_blocks, total, b2n);

    int threads = 256;
    int blocksB = (total * 32 + threads - 1) / threads;
    tof_kernel<<<blocksB, threads>>>(b1v, W2, b2v, out, total, b2n);
}

// round 5
// speedup vs baseline: 3.1068x; 1.2560x over previous
#include <cuda_runtime.h>
#include <math.h>

// Problem constants
#define NUM_R 8
#define KLEN  128
#define HID   32
#define LREC  4096
#define KP1   (KLEN + 1)
#define MAXB1 16
#define SPB   32              // samples per block (256 thr = 32 samples x 8 r)

// vy-folded fast-path table: contribution of receiver r, batch b1:
//   S = c.x + u * c.y   (vy baked in; b1/W2 not folded)
__device__ float2 g_C[MAXB1][NUM_R][KP1][HID];
// Raw prefix tables (PA, PB) for the general fallback path (also prep scratch)
__device__ float  g_P[NUM_R][KP1][2][HID];
// vy[b1][r] for the fallback path
__device__ float  g_vy[MAXB1][NUM_R];

// Table build: one block per (b1, r). Blocks with equal r write identical
// values to g_P (benign identical-value race); each block reads its own
// writes after __syncthreads.
__global__ void __launch_bounds__(256) prep_kernel(
    const float* __restrict__ W1, const float* __restrict__ rec)
{
    __shared__ float sTA[8][HID];
    __shared__ float sTB[8][HID];
    int r   = blockIdx.x & (NUM_R - 1);
    int b1  = blockIdx.x >> 3;
    int h   = threadIdx.x & 31;
    int seg = threadIdx.x >> 5;   // 0..7, 16 k's each
    const float inv = 1.0f / 16384.0f;

    int k0 = seg * 16;
    float a = 0.f, b = 0.f;
    if (seg == 0) { g_P[r][0][0][h] = 0.f; g_P[r][0][1][h] = 0.f; }
#pragma unroll
    for (int j = 0; j < 16; ++j) {
        int k = k0 + j;
        float w = W1[(r * KLEN + k) * HID + h];
        a += w;
        b += (float)k * w;
        g_P[r][k + 1][0][h] = a;
        g_P[r][k + 1][1][h] = b;
    }
    sTA[seg][h] = a;
    sTB[seg][h] = b;
    __syncthreads();

    float offA = 0.f, offB = 0.f;
    for (int s = 0; s < seg; ++s) { offA += sTA[s][h]; offB += sTB[s][h]; }
    if (seg > 0) {
#pragma unroll
        for (int j = 0; j < 16; ++j) {
            int k = k0 + j;
            g_P[r][k + 1][0][h] += offA;
            g_P[r][k + 1][1][h] += offB;
        }
    }
    __syncthreads();

    const float* rr = rec + (size_t)(b1 * NUM_R + r) * LREC;
    float vy = 0.5f * rr[2047] + 0.5f * rr[2048];
    if (threadIdx.x == 0) g_vy[b1][r] = vy;

    const float inv2 = 2.0f / 16384.0f;
    float Aend = g_P[r][KLEN][0][h];
    float Bend = g_P[r][KLEN][1][h];
    float Base = fmaf(-inv, Bend, Aend);
    for (int k = seg; k < KP1; k += 8) {
        float pa = g_P[r][k][0][h], pb = g_P[r][k][1][h];
        float2 c;
        c.x = vy * fmaf(inv2, pb, Base);
        c.y = vy * fmaf(2.0f, pa, -Aend);
        g_C[b1][r][k][h] = c;
    }
}

// Fused main kernel: 256 threads = 32 samples.
// Phase 1: thread (s_local, r) computes geometry -> smem (off, u).
// Phase 2: each warp handles 4 samples; lane = hidden unit.
__global__ void __launch_bounds__(256) tof_kernel(
    const float* __restrict__ sloc,   // (B1*B2, 3)
    const float* __restrict__ emit,   // (3,)
    const float* __restrict__ rloc,   // (R, 3)
    const float* __restrict__ b1v,    // (HID,)
    const float* __restrict__ W2,     // (HID,)
    const float* __restrict__ b2v,    // (1,)
    float* __restrict__ out,          // (B1*B2,)
    int total, int b2n)
{
    __shared__ float2 sg[SPB][NUM_R];
    __shared__ int s_bad;

    int tid  = threadIdx.x;
    int bbase = (int)blockIdx.x * SPB;
    const float inv = 1.0f / 16384.0f;

    if (tid == 0) s_bad = 0;
    __syncthreads();

    // ---- Phase 1: geometry ----
    {
        int s_local = tid >> 3;
        int r = tid & 7;
        int sample = bbase + s_local;
        if (sample < total) {
            int b1 = (int)((unsigned)sample / (unsigned)b2n);
            const float* sp = sloc + (size_t)sample * 3;
            float sx = sp[0], sy = sp[1], sz = sp[2];
            float dx = sx - emit[0], dy = sy - emit[1], dz = sz - emit[2];
            float de = sqrtf(dx * dx + dy * dy + dz * dz);
            const float* rp = rloc + r * 3;
            float qx = sx - rp[0], qy = sy - rp[1], qz = sz - rp[2];
            float dr = sqrtf(qx * qx + qy * qy + qz * qz);
            float tt = (de + dr) / 343.0f * 96000.0f;  // exact reference order
            int cs = (int)rintf(tt) - (KLEN / 2);
            int m0 = 4 * cs - 8192;
            int kb = max(min(-m0, KLEN), 0);
            bool ok = (m0 >= -16384) && (m0 <= 16384 - KLEN);
            int off = ((b1 * NUM_R + r) * KP1 + kb) * (HID * 8);  // byte offset
            sg[s_local][r] = make_float2(__int_as_float(off), (float)m0 * inv);
            if (!ok) atomicOr(&s_bad, 1);
        }
    }
    __syncthreads();

    // ---- Phase 2: table accumulation, 4 samples per warp ----
    int wid  = tid >> 5;
    int lane = tid & 31;
    int s0 = wid * 4;                   // local sample base for this warp
    bool bad = (s_bad != 0);

    float blane = b1v[lane];
    float wlane = W2[lane];
    float b2s   = b2v[0];

    float acc0 = 0.f, acc1 = 0.f, acc2 = 0.f, acc3 = 0.f;
    const char* basep = (const char*)(&g_C[0][0][0][0]) + lane * 8;

    if (!bad) {
#pragma unroll
        for (int r = 0; r < NUM_R; ++r) {
            float2 ga = sg[s0 + 0][r];
            float2 gb = sg[s0 + 1][r];
            float2 gc = sg[s0 + 2][r];
            float2 gd = sg[s0 + 3][r];
            float2 ca = *(const float2*)(basep + __float_as_int(ga.x));
            float2 cb = *(const float2*)(basep + __float_as_int(gb.x));
            float2 cc = *(const float2*)(basep + __float_as_int(gc.x));
            float2 cd = *(const float2*)(basep + __float_as_int(gd.x));
            acc0 = fmaf(ga.y, ca.y, acc0 + ca.x);
            acc1 = fmaf(gb.y, cb.y, acc1 + cb.x);
            acc2 = fmaf(gc.y, cc.y, acc2 + cc.x);
            acc3 = fmaf(gd.y, cd.y, acc3 + cd.x);
        }
    } else {
        // General fallback (rare): reconstruct m0 exactly from u.
        float* accs[4] = { &acc0, &acc1, &acc2, &acc3 };
#pragma unroll
        for (int j = 0; j < 4; ++j) {
            int sample = bbase + s0 + j;
            if (sample >= total) continue;
            int b1 = (int)((unsigned)sample / (unsigned)b2n);
            float a = 0.f;
#pragma unroll
            for (int r = 0; r < NUM_R; ++r) {
                float2 g = sg[s0 + j][r];
                int m0 = __float2int_rn(g.y * 16384.0f);
                float vy = g_vy[b1][r];
                int ka = max(min(-16384 - m0, KLEN), 0);
                int kb = max(min(-m0,          KLEN), 0);
                int kd = max(min(16384 - m0,   KLEN), 0);
                float m0f = (float)m0;
                if (kb > ka) {
                    float pa = g_P[r][kb][0][lane] - g_P[r][ka][0][lane];
                    float pb = g_P[r][kb][1][lane] - g_P[r][ka][1][lane];
                    a += vy * (fmaf(m0f, inv, 1.0f) * pa + inv * pb);
                }
                if (kd > kb) {
                    float pa = g_P[r][kd][0][lane] - g_P[r][kb][0][lane];
                    float pb = g_P[r][kd][1][lane] - g_P[r][kb][1][lane];
                    a += vy * (fmaf(-m0f, inv, 1.0f) * pa - inv * pb);
                }
            }
            *accs[j] = a;
        }
    }

    // ---- MLP head: relu(acc + b1) * W2, merged 4-sample warp reduction ----
    float c0 = fmaxf(acc0 + blane, 0.f) * wlane;
    float c1 = fmaxf(acc1 + blane, 0.f) * wlane;
    float c2 = fmaxf(acc2 + blane, 0.f) * wlane;
    float c3 = fmaxf(acc3 + blane, 0.f) * wlane;

    // Step A (xor 16): low half keeps s0/s2, high half keeps s1/s3.
    float t0 = __shfl_xor_sync(0xffffffffu, c0, 16);
    float t1 = __shfl_xor_sync(0xffffffffu, c1, 16);
    float t2 = __shfl_xor_sync(0xffffffffu, c2, 16);
    float t3 = __shfl_xor_sync(0xffffffffu, c3, 16);
    bool lo16 = lane < 16;
    float v = lo16 ? (c0 + t0) : (c1 + t1);   // lanes0-15: s0, 16-31: s1
    float w = lo16 ? (c2 + t2) : (c3 + t3);   // lanes0-15: s2, 16-31: s3
    // Step B (xor 8): groups of 8 lanes now each own one sample.
    float tv = __shfl_xor_sync(0xffffffffu, v, 8);
    float tw = __shfl_xor_sync(0xffffffffu, w, 8);
    float z = ((lane & 8) == 0) ? (v + tv) : (w + tw);
    // lanes 0-7: s0, 8-15: s2, 16-23: s1, 24-31: s3
    z += __shfl_xor_sync(0xffffffffu, z, 4);
    z += __shfl_xor_sync(0xffffffffu, z, 2);
    z += __shfl_xor_sync(0xffffffffu, z, 1);

    if ((lane & 7) == 0) {
        int j = ((lane >> 2) & 2) | (lane >> 4);   // 0->0, 8->2, 16->1, 24->3
        int idx = bbase + s0 + j;
        if (idx < total) out[idx] = z + b2s;
    }
}

extern "C" void kernel_launch(void* const* d_in, const int* in_sizes, int n_in,
                              void* d_out, int out_size) {
    const float* rec  = (const float*)d_in[0];
    const float* sloc = (const float*)d_in[1];
    const float* emit = (const float*)d_in[2];
    const float* rloc = (const float*)d_in[3];
    const float* W1   = (const float*)d_in[4];
    const float* b1v  = (const float*)d_in[5];
    const float* W2   = (const float*)d_in[6];
    const float* b2v  = (const float*)d_in[7];
    float* out = (float*)d_out;

    int nb1 = in_sizes[0] / (NUM_R * LREC);       // B1
    if (nb1 < 1) nb1 = 1;
    if (nb1 > MAXB1) nb1 = MAXB1;
    int total = out_size;                         // B1*B2 samples
    int b2n = total / nb1;

    prep_kernel<<<NUM_R * nb1, 256>>>(W1, rec);

    int blocks = (total + SPB - 1) / SPB;
    tof_kernel<<<blocks, 256>>>(sloc, emit, rloc, b1v, W2, b2v, out,
                                total, b2n);
}